// round 5
// baseline (speedup 1.0000x reference)
#include <cuda_runtime.h>
#include <cuda_bf16.h>
#include <cstdint>

// ===========================================================================
// GRU cell via mma.sync (sm_103 non-'a' target: tcgen05 unavailable).
// 3-term bf16 split: C = Ah*Bh + Al*Bh + Ah*Bl  (~2^-17 effective precision).
// One pack kernel emits bf16 hi/lo planes in ldmatrix-ready layout; main
// kernel is a 4-accumulator fused GEMM (r, z, n_i, n_h) + gate epilogue.
//   CTA tile M=128 x N=64, 512 threads = 16 warps (4m x 4n), warp m32 x n16.
//   3-stage cp.async pipeline, ONE __syncthreads per chunk.
// ===========================================================================

#define NT_COUNT 8           // 512 / 64
#define MT_COUNT 128         // 16384 / 128
#define NSTAGE 3

// packed A: [mt 128][chunk 32][plane 2][row 128][64B]  = 64 MB
// packed W: [nt 8][gate 3][chunk 32][plane 2][n 64][64B] = 6 MB
__device__ __align__(128) unsigned char g_Apack[128u * 32u * 2u * 128u * 64u];
__device__ __align__(128) unsigned char g_Wpack[8u * 3u * 32u * 2u * 64u * 64u];

// smem stage layout (stride 80B rows -> conflict-free ldmatrix):
//   A plane p:        p*10240 + r*80          (128 rows)
//   B gate g plane p: 20480 + ((g*2+p)*64 + n)*80
#define STAGE_BYTES 51200
#define SMEM_TOTAL (NSTAGE * STAGE_BYTES)   // 153600

__device__ __forceinline__ uint32_t smem_u32(const void* p) {
    uint32_t a;
    asm("{ .reg .u64 t; cvta.to.shared.u64 t, %1; cvt.u32.u64 %0, t; }"
        : "=r"(a) : "l"(p));
    return a;
}

__device__ __forceinline__ void cp16(uint32_t dst, const void* src) {
    asm volatile("cp.async.cg.shared.global [%0], [%1], 16;"
                 :: "r"(dst), "l"(src) : "memory");
}
__device__ __forceinline__ void cp_commit() {
    asm volatile("cp.async.commit_group;" ::: "memory");
}
template <int N> __device__ __forceinline__ void cp_wait() {
    asm volatile("cp.async.wait_group %0;" :: "n"(N) : "memory");
}

__device__ __forceinline__ void ldm4(uint32_t r[4], uint32_t addr) {
    asm volatile("ldmatrix.sync.aligned.m8n8.x4.shared.b16 {%0,%1,%2,%3}, [%4];"
                 : "=r"(r[0]), "=r"(r[1]), "=r"(r[2]), "=r"(r[3]) : "r"(addr));
}

__device__ __forceinline__ void mma16(float c[4], const uint32_t a[4],
                                      uint32_t b0, uint32_t b1) {
    asm volatile(
        "mma.sync.aligned.m16n8k16.row.col.f32.bf16.bf16.f32 "
        "{%0,%1,%2,%3}, {%4,%5,%6,%7}, {%8,%9}, {%0,%1,%2,%3};\n"
        : "+f"(c[0]), "+f"(c[1]), "+f"(c[2]), "+f"(c[3])
        : "r"(a[0]), "r"(a[1]), "r"(a[2]), "r"(a[3]), "r"(b0), "r"(b1));
}

__device__ __forceinline__ uint32_t pack_hi(float a, float b, uint32_t& lo) {
    __nv_bfloat16 ha = __float2bfloat16(a);
    __nv_bfloat16 hb = __float2bfloat16(b);
    float ra = a - __bfloat162float(ha);
    float rb = b - __bfloat162float(hb);
    __nv_bfloat162 hw; hw.x = ha; hw.y = hb;
    __nv_bfloat162 lw = __floats2bfloat162_rn(ra, rb);
    lo = *reinterpret_cast<uint32_t*>(&lw);
    return *reinterpret_cast<uint32_t*>(&hw);
}

// ---------------------------------------------------------------------------
// Merged pack kernel. Blocks [0,4096): A part (c = bx&31, mt = bx>>5).
// Blocks [4096,4864): W part (c = w&31, ntg = w>>5; nt = ntg/3, g = ntg%3).
__global__ __launch_bounds__(256) void pack_all(
    const float* __restrict__ x, const float* __restrict__ hs,
    const float* __restrict__ Wir, const float* __restrict__ Whr,
    const float* __restrict__ Wiz, const float* __restrict__ Whz,
    const float* __restrict__ Win, const float* __restrict__ Whn) {
    __shared__ float stg[32][65];
    const int bx = blockIdx.x;
    if (bx < 4096) {
        const int c = bx & 31, mt = bx >> 5;
        const float* S = (c < 16) ? x : hs;
        const int k0 = (c & 15) * 32;
        const size_t mrow = (size_t)mt * 128;
        unsigned char* hiP = g_Apack + ((size_t)(mt * 32 + c) * 2) * 8192;
        unsigned char* loP = hiP + 8192;
        #pragma unroll
        for (int it = 0; it < 8; ++it) {
            int id = it * 256 + threadIdx.x;   // 2048 float2
            int r = id >> 4, w = id & 15;
            float2 v = *reinterpret_cast<const float2*>(
                S + (mrow + r) * 512 + k0 + 2 * w);
            uint32_t lo, hi = pack_hi(v.x, v.y, lo);
            *reinterpret_cast<uint32_t*>(hiP + r * 64 + w * 4) = hi;
            *reinterpret_cast<uint32_t*>(loP + r * 64 + w * 4) = lo;
        }
    } else {
        const int w = bx - 4096;
        const int c = w & 31;
        const int ntg = w >> 5;                // 0..23
        const int nt = ntg / 3, g = ntg % 3;
        const float* W = (c < 16)
            ? ((g == 0) ? Wir : (g == 1) ? Wiz : Win)
            : ((g == 0) ? Whr : (g == 1) ? Whz : Whn);
        const int k0 = (c & 15) * 32, n0 = nt * 64;
        #pragma unroll
        for (int it = 0; it < 8; ++it) {       // 2048 floats: 32k x 64n
            int id = it * 256 + threadIdx.x;
            int k = id >> 6, n = id & 63;
            stg[k][n] = W[(size_t)(k0 + k) * 512 + n0 + n];
        }
        __syncthreads();
        unsigned char* hiP = g_Wpack + ((size_t)((nt * 3 + g) * 32 + c) * 2) * 4096;
        unsigned char* loP = hiP + 4096;
        #pragma unroll
        for (int it = 0; it < 4; ++it) {       // 1024 word-pairs
            int id = it * 256 + threadIdx.x;
            int n = id >> 4, q = id & 15;
            uint32_t lo, hi = pack_hi(stg[2 * q][n], stg[2 * q + 1][n], lo);
            *reinterpret_cast<uint32_t*>(hiP + n * 64 + q * 4) = hi;
            *reinterpret_cast<uint32_t*>(loP + n * 64 + q * 4) = lo;
        }
    }
}

// ---------------------------------------------------------------------------
// issue one stage: 2560 cp16 ops, 512 threads -> 5 iterations.
__device__ __forceinline__ void issue_stage(uint32_t sbase, int nt, int mt, int c) {
    const int tid = threadIdx.x;
    const unsigned char* Ac = g_Apack + ((size_t)(mt * 32 + c) * 2) * 8192;
    const unsigned char* Wc = g_Wpack + ((size_t)(nt * 3 * 32) * 2) * 4096;
    #pragma unroll
    for (int it = 0; it < 5; ++it) {
        int id = it * 512 + tid;
        if (id < 1024) {                       // A: plane(2) x row(128) x ch(4)
            int p = id >> 9, rem = id & 511;
            int r = rem >> 2, ch = rem & 3;
            cp16(sbase + p * 10240 + r * 80 + ch * 16,
                 Ac + p * 8192 + r * 64 + ch * 16);
        } else {                               // B: gp(6) x n(64) x ch(4)
            int v = id - 1024;
            int gp = v >> 8, rem = v & 255;
            int n = rem >> 2, ch = rem & 3;
            int g = gp >> 1, p = gp & 1;
            cp16(sbase + 20480 + (gp * 64 + n) * 80 + ch * 16,
                 Wc + ((size_t)(g * 32 + c) * 2 + p) * 4096 + n * 64 + ch * 16);
        }
    }
}

#define GATE_MMA(ACC, BH, BL)                                         \
    do {                                                              \
        mma16(ACC[0][0], Ah0, BH[0], BH[1]);                          \
        mma16(ACC[0][1], Ah0, BH[2], BH[3]);                          \
        mma16(ACC[1][0], Ah1, BH[0], BH[1]);                          \
        mma16(ACC[1][1], Ah1, BH[2], BH[3]);                          \
        mma16(ACC[0][0], Al0, BH[0], BH[1]);                          \
        mma16(ACC[0][1], Al0, BH[2], BH[3]);                          \
        mma16(ACC[1][0], Al1, BH[0], BH[1]);                          \
        mma16(ACC[1][1], Al1, BH[2], BH[3]);                          \
        mma16(ACC[0][0], Ah0, BL[0], BL[1]);                          \
        mma16(ACC[0][1], Ah0, BL[2], BL[3]);                          \
        mma16(ACC[1][0], Ah1, BL[0], BL[1]);                          \
        mma16(ACC[1][1], Ah1, BL[2], BL[3]);                          \
    } while (0)

__device__ __forceinline__ void compute_chunk(
    uint32_t sbase, int wm, int wn, int lane,
    float accR[2][2][4], float accZ[2][2][4], float accN[2][2][4]) {
    const int rowA = (lane & 7) + ((lane >> 3) & 1) * 8;
    const int kbA  = (lane >> 4) * 16;
    const int rowB = (lane & 7) + (lane >> 4) * 8;
    const int kbB  = ((lane >> 3) & 1) * 16;
    const uint32_t aAddr = sbase + (wm + rowA) * 80 + kbA;
    const uint32_t bAddr = sbase + 20480 + (wn + rowB) * 80 + kbB;

    #pragma unroll
    for (int ks = 0; ks < 2; ++ks) {
        uint32_t Ah0[4], Ah1[4], Al0[4], Al1[4];
        ldm4(Ah0, aAddr + ks * 32);
        ldm4(Ah1, aAddr + ks * 32 + 1280);          // +16 rows
        ldm4(Al0, aAddr + ks * 32 + 10240);         // lo plane
        ldm4(Al1, aAddr + ks * 32 + 10240 + 1280);

        uint32_t Bh[4], Bl[4];
        // gate r (g=0): planes at +0 / +5120
        ldm4(Bh, bAddr + ks * 32);
        ldm4(Bl, bAddr + ks * 32 + 5120);
        GATE_MMA(accR, Bh, Bl);
        // gate z (g=1): +10240 / +15360
        ldm4(Bh, bAddr + ks * 32 + 10240);
        ldm4(Bl, bAddr + ks * 32 + 15360);
        GATE_MMA(accZ, Bh, Bl);
        // gate n (g=2): +20480 / +25600
        ldm4(Bh, bAddr + ks * 32 + 20480);
        ldm4(Bl, bAddr + ks * 32 + 25600);
        GATE_MMA(accN, Bh, Bl);
    }
}

__global__ void __launch_bounds__(512, 1) gru_main(
    const float* __restrict__ hs,
    const float* __restrict__ br, const float* __restrict__ bz,
    const float* __restrict__ bn, float* __restrict__ out) {
    extern __shared__ unsigned char smem_raw[];
    const uint32_t smem = smem_u32(smem_raw);

    const int tid = threadIdx.x;
    const int wid = tid >> 5, lane = tid & 31;
    const int wm = (wid & 3) * 32;
    const int wn = (wid >> 2) * 16;       // 0..3 -> 0,16,32,48
    const int nt = blockIdx.x;            // 0..7
    const int mt = blockIdx.y;            // 0..127

    float aR[2][2][4] = {}, aZ[2][2][4] = {}, aNi[2][2][4] = {}, aNh[2][2][4] = {};

    issue_stage(smem, nt, mt, 0);
    cp_commit();
    issue_stage(smem + STAGE_BYTES, nt, mt, 1);
    cp_commit();

    // Single-sync multistage:
    //   wait(stage c) -> sync (all warps done with stage c-1)
    //   -> issue stage c+2 into buffer (c+2)%3 -> compute stage c.
    int sidx = 0;                  // c % 3
    for (int c = 0; c < 32; ++c) {
        if (c + 1 < 32) cp_wait<1>(); else cp_wait<0>();
        __syncthreads();
        if (c + 2 < 32) {
            int widx = sidx + 2 >= NSTAGE ? sidx + 2 - NSTAGE : sidx + 2;
            issue_stage(smem + widx * STAGE_BYTES, nt, mt, c + 2);
            cp_commit();
        }
        const uint32_t sbase = smem + sidx * STAGE_BYTES;
        if (c < 16) compute_chunk(sbase, wm, wn, lane, aR, aZ, aNi);
        else        compute_chunk(sbase, wm, wn, lane, aR, aZ, aNh);
        sidx = (sidx + 1 >= NSTAGE) ? 0 : sidx + 1;
    }

    // ---- epilogue ----
    #pragma unroll
    for (int mi = 0; mi < 2; ++mi)
    #pragma unroll
    for (int ni = 0; ni < 2; ++ni)
    #pragma unroll
    for (int i = 0; i < 4; ++i) {
        int rr = mt * 128 + wm + mi * 16 + (lane >> 2) + ((i >> 1) << 3);
        int cc = nt * 64 + wn + ni * 8 + 2 * (lane & 3) + (i & 1);
        float pr = aR[mi][ni][i] + __ldg(br + cc);
        float pz = aZ[mi][ni][i] + __ldg(bz + cc);
        float rg = 1.0f / (1.0f + __expf(-pr));
        float zg = 1.0f / (1.0f + __expf(-pz));
        float ng = tanhf(aNi[mi][ni][i] + rg * aNh[mi][ni][i] + __ldg(bn + cc));
        float hv = hs[(size_t)rr * 512 + cc];
        out[(size_t)rr * 512 + cc] = (1.0f - zg) * ng + zg * hv;
    }
}

// ---------------------------------------------------------------------------
extern "C" void kernel_launch(void* const* d_in, const int* in_sizes, int n_in,
                              void* d_out, int out_size) {
    (void)in_sizes; (void)n_in; (void)out_size;
    const float* x   = (const float*)d_in[0];
    const float* h   = (const float*)d_in[1];
    const float* Wir = (const float*)d_in[2];
    const float* Whr = (const float*)d_in[3];
    const float* br  = (const float*)d_in[4];
    const float* Wiz = (const float*)d_in[5];
    const float* Whz = (const float*)d_in[6];
    const float* bz  = (const float*)d_in[7];
    const float* Win = (const float*)d_in[8];
    const float* Whn = (const float*)d_in[9];
    const float* bn  = (const float*)d_in[10];

    static_assert(SMEM_TOTAL == 153600, "smem layout");
    cudaFuncSetAttribute(gru_main, cudaFuncAttributeMaxDynamicSharedMemorySize,
                         SMEM_TOTAL);
    cudaFuncSetAttribute(gru_main, cudaFuncAttributePreferredSharedMemoryCarveout,
                         cudaSharedmemCarveoutMaxShared);

    pack_all<<<4864, 256>>>(x, h, Wir, Whr, Wiz, Whz, Win, Whn);
    gru_main<<<dim3(NT_COUNT, MT_COUNT), 512, SMEM_TOTAL>>>(
        h, br, bz, bn, (float*)d_out);
}